// round 3
// baseline (speedup 1.0000x reference)
#include <cuda_runtime.h>
#include <stdint.h>
#include <math.h>

#define NB 2048
#define ND 256
#define NDT 768
#define HS 512   // hash slots per subset

// accumulators: [0]=mse sumsq, [1..7]=entropy row-sums S1,S2,S3,S13,S23,S12,S123
__device__ double g_acc[8];
__device__ double g_ck[14];          // ce,kl sums per 7 masks
__device__ unsigned int g_minbits[3];
__device__ unsigned int g_done;
__device__ float g_stats[NB * 18];   // per row, per k: mD, sD, tO, uD, mO, sO

__device__ __forceinline__ unsigned int fkey(float f) {
    unsigned int u = __float_as_uint(f);
    return (u & 0x80000000u) ? ~u : (u | 0x80000000u);
}
__device__ __forceinline__ float funkey(unsigned int u) {
    return __uint_as_float((u & 0x80000000u) ? (u & 0x7FFFFFFFu) : ~u);
}

__global__ void init_kernel() {
    int t = threadIdx.x;
    if (t < 8) g_acc[t] = 0.0;
    if (t < 14) g_ck[t] = 0.0;
    if (t < 3) g_minbits[t] = 0xFFFFFFFFu;
    if (t == 0) g_done = 0u;
}

// ---------------- per-row softmax stats + global mins + fused MSE ----------------
__global__ void stats_kernel(const float* __restrict__ d1, const float* __restrict__ d2,
                             const float* __restrict__ d3,
                             const float* __restrict__ o1, const float* __restrict__ o2,
                             const float* __restrict__ o3,
                             const float* __restrict__ data, const float* __restrict__ outp) {
    int tid = blockIdx.x * blockDim.x + threadIdx.x;
    int lane = threadIdx.x & 31;

    // --- fused MSE over [NB, NDT] via float4 grid-stride ---
    {
        const float4* a = (const float4*)data;
        const float4* b = (const float4*)outp;
        int n4 = NB * NDT / 4;
        int stride = gridDim.x * blockDim.x;
        float s = 0.f;
        for (int i = tid; i < n4; i += stride) {
            float4 x = a[i], y = b[i];
            float e0 = x.x - y.x, e1 = x.y - y.y, e2 = x.z - y.z, e3 = x.w - y.w;
            s += e0 * e0 + e1 * e1 + e2 * e2 + e3 * e3;
        }
        for (int o = 16; o; o >>= 1) s += __shfl_xor_sync(0xffffffffu, s, o);
        if (lane == 0) atomicAdd(&g_acc[0], (double)s);
    }

    // --- per-row stats: one warp per row ---
    int gw = tid >> 5;
    if (gw >= NB) return;
    const float* ds[3] = {d1, d2, d3};
    const float* os[3] = {o1, o2, o3};
#pragma unroll
    for (int k = 0; k < 3; k++) {
        const float* dp = ds[k] + gw * ND;
        const float* op = os[k] + gw * ND;
        float vd[8], vo[8];
#pragma unroll
        for (int i = 0; i < 8; i++) { vd[i] = dp[lane + 32 * i]; vo[i] = op[lane + 32 * i]; }
        float mD = -INFINITY, mO = -INFINITY, mn = INFINITY;
#pragma unroll
        for (int i = 0; i < 8; i++) {
            mD = fmaxf(mD, vd[i]); mO = fmaxf(mO, vo[i]); mn = fminf(mn, vd[i]);
        }
        for (int o = 16; o; o >>= 1) {
            mD = fmaxf(mD, __shfl_xor_sync(0xffffffffu, mD, o));
            mO = fmaxf(mO, __shfl_xor_sync(0xffffffffu, mO, o));
            mn = fminf(mn, __shfl_xor_sync(0xffffffffu, mn, o));
        }
        float sD = 0.f, tO = 0.f, uD = 0.f, sO = 0.f;
#pragma unroll
        for (int i = 0; i < 8; i++) {
            float e = expf(vd[i] - mD);
            sD += e; tO += e * vo[i]; uD += e * vd[i];
            sO += expf(vo[i] - mO);
        }
        for (int o = 16; o; o >>= 1) {
            sD += __shfl_xor_sync(0xffffffffu, sD, o);
            tO += __shfl_xor_sync(0xffffffffu, tO, o);
            uD += __shfl_xor_sync(0xffffffffu, uD, o);
            sO += __shfl_xor_sync(0xffffffffu, sO, o);
        }
        if (lane == 0) {
            float* st = g_stats + gw * 18 + k * 6;
            st[0] = mD; st[1] = sD; st[2] = tO; st[3] = uD; st[4] = mO; st[5] = sO;
            atomicMin(&g_minbits[k], fkey(mn));
        }
    }
}

// packed-slot insert: word = key<<9 | count (count <= 256 fits 9 bits, keys <= 23 bits)
__device__ __forceinline__ uint32_t hinsert(uint32_t* table, uint32_t key) {
    uint32_t h = (key * 2654435769u) >> 23;
    uint32_t packed = (key << 9) | 1u;
    for (;;) {
        uint32_t old = atomicCAS(&table[h], 0u, packed);
        if (old == 0u) return h;
        if ((old >> 9) == key) { atomicAdd(&table[h], 1u); return h; }
        h = (h + 1) & (HS - 1);
    }
}

// ---------------- per-row joint entropies: 7 concurrent hash tables ----------------
__global__ void entropy_kernel(const float* __restrict__ d1, const float* __restrict__ d2,
                               const float* __restrict__ d3) {
    __shared__ uint32_t tab[7 * HS];
    __shared__ float red[8 * 7];
    int row = blockIdx.x, t = threadIdx.x;
    float lo1 = floorf(funkey(g_minbits[0]));
    float lo2 = floorf(funkey(g_minbits[1]));
    float lo3 = floorf(funkey(g_minbits[2]));
    int idx = row * ND + t;
    uint32_t lab0 = (uint32_t)(int)floorf(__fdiv_rn(d1[idx] - lo1, 0.01f));
    uint32_t lab1 = (uint32_t)(int)floorf(__fdiv_rn(d2[idx] - lo2, 0.01f));
    uint32_t lab2 = (uint32_t)(int)floorf(__fdiv_rn(d3[idx] - lo3, 0.01f));

#pragma unroll
    for (int i = 0; i < 7 * HS / ND; i++) tab[t + i * ND] = 0u;
    __syncthreads();

    // singles (concurrent, independent tables)
    uint32_t s0 = hinsert(tab + 0 * HS, lab0);
    uint32_t s1 = hinsert(tab + 1 * HS, lab1);
    uint32_t s2 = hinsert(tab + 2 * HS, lab2);
    __syncthreads();

    // pairs (keys are 9-bit slot-id pairs, injective per row)
    uint32_t s3 = hinsert(tab + 3 * HS, s0 | (s2 << 9));
    uint32_t s4 = hinsert(tab + 4 * HS, s1 | (s2 << 9));
    uint32_t s5 = hinsert(tab + 5 * HS, s0 | (s1 << 9));
    __syncthreads();

    // triple via pair-12 slot id + slot2
    uint32_t s6 = hinsert(tab + 6 * HS, s5 | (s2 << 9));
    __syncthreads();

    uint32_t sl[7] = {s0, s1, s2, s3, s4, s5, s6};
    float lg[7];
#pragma unroll
    for (int s = 0; s < 7; s++)
        lg[s] = logf((float)(tab[s * HS + sl[s]] & 0x1FFu) * (1.0f / 256.0f));

    int lane = t & 31, w = t >> 5;
#pragma unroll
    for (int k = 0; k < 7; k++) {
        float x = lg[k];
        for (int o = 16; o; o >>= 1) x += __shfl_xor_sync(0xffffffffu, x, o);
        if (lane == 0) red[w * 7 + k] = x;
    }
    __syncthreads();
    if (t < 7) {
        double ssum = 0.0;
        for (int w2 = 0; w2 < 8; w2++) ssum += (double)red[w2 * 7 + t];
        atomicAdd(&g_acc[1 + t], -ssum * (1.0 / 256.0));
    }
}

// ---------------- per-row softmax-entropy (ce/kl) + fused finish (last block) ----------------
__global__ void hsoft_kernel(float* __restrict__ out) {
    const int masks[7] = {1, 2, 4, 5, 6, 3, 7}; // {1},{2},{3},{1,3},{2,3},{1,2},{1,2,3}
    int row = blockIdx.x * blockDim.x + threadIdx.x;
    float ce[7], kl[7];
    {
        float st[18];
#pragma unroll
        for (int i = 0; i < 18; i++) st[i] = g_stats[row * 18 + i];
#pragma unroll
        for (int s = 0; s < 7; s++) {
            int m = masks[s];
            float M = -INFINITY, MO = -INFINITY;
#pragma unroll
            for (int k = 0; k < 3; k++)
                if (m & (1 << k)) { M = fmaxf(M, st[k * 6 + 0]); MO = fmaxf(MO, st[k * 6 + 4]); }
            float S = 0.f, T = 0.f, U = 0.f, SO = 0.f;
#pragma unroll
            for (int k = 0; k < 3; k++)
                if (m & (1 << k)) {
                    float w = expf(st[k * 6 + 0] - M);
                    S += st[k * 6 + 1] * w;
                    T += st[k * 6 + 2] * w;
                    U += st[k * 6 + 3] * w;
                    SO += st[k * 6 + 5] * expf(st[k * 6 + 4] - MO);
                }
            float lseD = M + logf(S);
            float lseO = MO + logf(SO);
            float Spo = T / S, Spd = U / S;
            ce[s] = lseO - Spo;
            kl[s] = (Spd - lseD) - (Spo - lseO);
        }
    }
    int lane = threadIdx.x & 31;
#pragma unroll
    for (int s = 0; s < 7; s++) {
        float c = ce[s], k = kl[s];
        for (int o = 16; o; o >>= 1) {
            c += __shfl_xor_sync(0xffffffffu, c, o);
            k += __shfl_xor_sync(0xffffffffu, k, o);
        }
        if (lane == 0) {
            atomicAdd(&g_ck[s], (double)c);
            atomicAdd(&g_ck[7 + s], (double)k);
        }
    }

    // last-block finish
    __syncthreads();
    __shared__ bool is_last;
    if (threadIdx.x == 0) {
        __threadfence();
        unsigned int old = atomicInc(&g_done, gridDim.x - 1);
        is_last = (old == gridDim.x - 1);
    }
    __syncthreads();
    if (is_last && threadIdx.x == 0) {
        double Hout[7];
        for (int s = 0; s < 7; s++) {
            int C = ND * __popc(masks[s]);
            Hout[s] = g_ck[s] / (double)NB - g_ck[7 + s] / ((double)NB * (double)C);
        }
        double Hd1 = g_acc[1] / NB, Hd2 = g_acc[2] / NB, Hd3 = g_acc[3] / NB;
        double Hin13 = g_acc[4] / NB, Hin23 = g_acc[5] / NB, Hin12 = g_acc[6] / NB;
        double H1 = Hd1 - Hout[0];
        double H2 = Hd2 - Hout[1];
        double H3 = Hd3 - Hout[2];
        double data13 = Hd1 + Hd3 - Hin13;
        double data23 = Hd2 + Hd3 - Hin23;
        double data12 = Hd1 + Hd2 - Hin12;
        double lab13 = Hout[0] + Hout[2] - Hout[3];
        double lab23 = Hout[1] + Hout[2] - Hout[4];
        double lab12 = Hout[0] + Hout[1] - Hout[5];
        double MI13 = lab13 - data13, MI23 = lab23 - data23, MI12 = lab12 - data12;
        double aveDataCMI = g_acc[4] + g_acc[5] - g_acc[3] - g_acc[7];
        double aveLabCMI = Hout[4] - Hout[2] + Hout[3] - Hout[6];
        double CMI = aveLabCMI - aveDataCMI;
        double mse = 0.5 * (g_acc[0] / ((double)NB * (double)NDT));
        double loss = 0.5 * mse
                    + 0.25 * (H1 * H1 + H2 * H2 + H3 * H3)
                    + 0.25 * (MI13 * MI13 + MI23 * MI23 + MI12 * MI12 + CMI * CMI);
        out[0] = (float)loss;
    }
}

extern "C" void kernel_launch(void* const* d_in, const int* in_sizes, int n_in,
                              void* d_out, int out_size) {
    (void)in_sizes; (void)n_in; (void)out_size;
    const float* data  = (const float*)d_in[0];
    const float* data1 = (const float*)d_in[1];
    const float* data2 = (const float*)d_in[2];
    const float* data3 = (const float*)d_in[3];
    const float* out1  = (const float*)d_in[4];
    const float* out2  = (const float*)d_in[5];
    const float* out3  = (const float*)d_in[6];
    const float* outp  = (const float*)d_in[7];

    init_kernel<<<1, 32>>>();
    stats_kernel<<<NB / 8, 256>>>(data1, data2, data3, out1, out2, out3, data, outp);
    entropy_kernel<<<NB, 256>>>(data1, data2, data3);
    hsoft_kernel<<<NB / 256, 256>>>((float*)d_out);
}